// round 12
// baseline (speedup 1.0000x reference)
#include <cuda_runtime.h>
#include <math.h>
#include <stdint.h>

#define LDIM 4096
#define NPTS 2048
#define WPIX 640.0f
#define HPIX 480.0f
#define GRID 608                 // 152 SMs x 4 blocks: one perfectly even wave
#define MAXR 7                   // ceil(4096/608)

// 256-bit load (kept with evict_last; sm_103 requires v8.b32 form).
__device__ __forceinline__ void ldg256(const float* __restrict__ p,
                                       float4& a, float4& b)
{
    asm volatile("ld.global.nc.L2::evict_last.v8.b32 "
                 "{%0,%1,%2,%3,%4,%5,%6,%7}, [%8];"
                 : "=f"(a.x), "=f"(a.y), "=f"(a.z), "=f"(a.w),
                   "=f"(b.x), "=f"(b.y), "=f"(b.z), "=f"(b.w)
                 : "l"(p));
}

// ---------------------------------------------------------------------------
// Persistent grid-stride kernel with register double-buffering.
// Block b processes rows b, b+608, ... (6 or 7 rows). While row k is being
// accumulated, the two LDG.256 for row k+1 are already in flight (issued
// before consumption; asm volatile preserves order). No barriers inside the
// loop; per-row moments land in disjoint smem slots. Final: <=7 concurrent
// eigensolves in threads 0..6.
// ---------------------------------------------------------------------------
__global__ void __launch_bounds__(256, 4)
fused_kernel(const float* __restrict__ in,
             const float* __restrict__ center,
             const float* __restrict__ alpha_p,
             float* __restrict__ out)
{
    const int b = blockIdx.x;
    const int t = threadIdx.x;

    const float cx = center[0];
    const float cy = center[1];
    const float alpha = alpha_p[0];
    const float invW = 1.0f / WPIX;
    const float invH = 1.0f / HPIX;

    __shared__ float moments[MAXR][5];
    if (t < MAXR * 5) ((float*)moments)[t] = 0.f;
    __syncthreads();

    // Register double buffer: 4 float4 per row per thread (2 x LDG.256).
    float4 buf[2][4];

    // Prologue: load row 0 of this block.
    {
        const float* p = in + (size_t)b * (NPTS * 2) + t * 8;
        ldg256(p,        buf[0][0], buf[0][1]);
        ldg256(p + 2048, buf[0][2], buf[0][3]);
    }

    #pragma unroll
    for (int k = 0; k < MAXR; k++) {
        const int rr = b + k * GRID;
        if (rr >= LDIM) break;

        // Prefetch next row into the other buffer BEFORE consuming this one.
        const int rn = rr + GRID;
        if (rn < LDIM) {
            const float* p = in + (size_t)rn * (NPTS * 2) + t * 8;
            ldg256(p,        buf[(k + 1) & 1][0], buf[(k + 1) & 1][1]);
            ldg256(p + 2048, buf[(k + 1) & 1][2], buf[(k + 1) & 1][3]);
        }

        float Sxx = 0.f, Sxy = 0.f, Syy = 0.f, Sx = 0.f, Sy = 0.f;

        #pragma unroll
        for (int i = 0; i < 4; i++) {
            float4 v = buf[k & 1][i];

            float sx = v.x * invW - cx;
            float sy = v.y * invH - cy;
            float r2 = sx * sx + sy * sy;
            float f  = 1.0f + alpha * r2;
            float ux = f * sx + cx;
            float uy = f * sy + cy;
            Sxx += ux * ux; Sxy += ux * uy; Syy += uy * uy; Sx += ux; Sy += uy;

            sx = v.z * invW - cx;
            sy = v.w * invH - cy;
            r2 = sx * sx + sy * sy;
            f  = 1.0f + alpha * r2;
            ux = f * sx + cx;
            uy = f * sy + cy;
            Sxx += ux * ux; Sxy += ux * uy; Syy += uy * uy; Sx += ux; Sy += uy;
        }

        #pragma unroll
        for (int o = 16; o > 0; o >>= 1) {
            Sxx += __shfl_xor_sync(0xffffffffu, Sxx, o);
            Sxy += __shfl_xor_sync(0xffffffffu, Sxy, o);
            Syy += __shfl_xor_sync(0xffffffffu, Syy, o);
            Sx  += __shfl_xor_sync(0xffffffffu, Sx,  o);
            Sy  += __shfl_xor_sync(0xffffffffu, Sy,  o);
        }

        if ((t & 31) == 0) {
            atomicAdd(&moments[k][0], Sxx);
            atomicAdd(&moments[k][1], Sxy);
            atomicAdd(&moments[k][2], Syy);
            atomicAdd(&moments[k][3], Sx);
            atomicAdd(&moments[k][4], Sy);
        }
    }

    __syncthreads();

    // Deferred concurrent eigensolves (threads 0..MAXR-1).
    if (t < MAXR) {
        const int rr = b + t * GRID;
        if (rr < LDIM) {
            const float* sm = moments[t];
            float m00 =  sm[0];
            float m01 =  sm[1];
            float m11 =  sm[2];
            float m02 = -sm[3];
            float m12 = -sm[4];
            float m22 =  (float)NPTS;

            // Newton on det(M - lam I) from lam = 0: monotone convergence
            // for SPD M with well-separated lam_min.
            float lam = 0.0f;
            #pragma unroll
            for (int it = 0; it < 6; it++) {
                float a00 = m00 - lam, a11 = m11 - lam, a22 = m22 - lam;
                float M0 = a11 * a22 - m12 * m12;
                float M1 = a00 * a22 - m02 * m02;
                float M2 = a00 * a11 - m01 * m01;
                float det = a00 * M0
                          - m01 * (m01 * a22 - m12 * m02)
                          + m02 * (m01 * m12 - a11 * m02);
                float dp = M0 + M1 + M2;       // = -p'(lam)
                lam += det / fmaxf(dp, 1e-20f);
            }

            float c00 = m00 - lam, c11 = m11 - lam, c22 = m22 - lam;

            float x0 = m01 * m12 - m02 * c11;
            float y0 = m02 * m01 - c00 * m12;
            float z0 = c00 * c11 - m01 * m01;
            float n0 = x0 * x0 + y0 * y0 + z0 * z0;

            float x1 = m01 * c22 - m02 * m12;
            float y1 = m02 * m02 - c00 * c22;
            float z1 = c00 * m12 - m01 * m02;
            float n1 = x1 * x1 + y1 * y1 + z1 * z1;

            float x2 = c11 * c22 - m12 * m12;
            float y2 = m12 * m02 - m01 * c22;
            float z2 = m01 * m12 - c11 * m02;
            float n2 = x2 * x2 + y2 * y2 + z2 * z2;

            float vx = x0, vy = y0, vz = z0, nbest = n0;
            if (n1 > nbest) { vx = x1; vy = y1; vz = z1; nbest = n1; }
            if (n2 > nbest) { vx = x2; vy = y2; vz = z2; nbest = n2; }

            float vMv = m00 * vx * vx + m11 * vy * vy + m22 * vz * vz
                      + 2.0f * (m01 * vx * vy + m02 * vx * vz + m12 * vy * vz);
            float denom = vx * vx + vy * vy;
            out[rr] = vMv / denom;
        }
    }
}

extern "C" void kernel_launch(void* const* d_in, const int* in_sizes, int n_in,
                              void* d_out, int out_size)
{
    const float* input  = (const float*)d_in[0];
    const float* center = (const float*)d_in[1];
    const float* alpha  = (const float*)d_in[2];
    float* out = (float*)d_out;

    fused_kernel<<<GRID, 256>>>(input, center, alpha, out);
}

// round 13
// speedup vs baseline: 1.1626x; 1.1626x over previous
#include <cuda_runtime.h>
#include <math.h>

#define LDIM 4096
#define NPTS 2048
#define WPIX 640.0f
#define HPIX 480.0f

// 256-bit load with L2 evict_last hint (sm_103 requires v8.b32 form).
__device__ __forceinline__ void ldg256(const float* __restrict__ p,
                                       float4& a, float4& b)
{
    asm volatile("ld.global.nc.L2::evict_last.v8.b32 "
                 "{%0,%1,%2,%3,%4,%5,%6,%7}, [%8];"
                 : "=f"(a.x), "=f"(a.y), "=f"(a.z), "=f"(a.w),
                   "=f"(b.x), "=f"(b.y), "=f"(b.z), "=f"(b.w)
                 : "l"(p));
}

// ---------------------------------------------------------------------------
// One block per l. 128 threads, 4 front-batched LDG.256 per thread (16KB per
// block, true MLP=4 thanks to the (128,8) register budget). This design sits
// at the GB300 LTS path-independent throughput cap (~5.2 TB/s for this
// footprint): 67MB / cap ~= 12.8us. Accumulation consumes loads in issue
// order so early math overlaps in-flight later loads; no staging array.
// Thread 0 finishes with the trig-free Newton eigensolve.
// ---------------------------------------------------------------------------
__global__ void __launch_bounds__(128, 8)
fused_kernel(const float* __restrict__ in,
             const float* __restrict__ center,
             const float* __restrict__ alpha_p,
             float* __restrict__ out)
{
    const int l = blockIdx.x;
    const int t = threadIdx.x;

    const float cx = center[0];
    const float cy = center[1];
    const float alpha = alpha_p[0];
    const float invW = 1.0f / WPIX;
    const float invH = 1.0f / HPIX;

    const float* base = in + (size_t)l * (NPTS * 2);

    float4 v0, v1, v2, v3, v4, v5, v6, v7;
    ldg256(base +        t * 8, v0, v1);
    ldg256(base + 1024 + t * 8, v2, v3);
    ldg256(base + 2048 + t * 8, v4, v5);
    ldg256(base + 3072 + t * 8, v6, v7);

    float Sxx = 0.f, Sxy = 0.f, Syy = 0.f, Sx = 0.f, Sy = 0.f;

    #define ACC(v)                                                          \
    {                                                                       \
        float sx = (v).x * invW - cx;                                       \
        float sy = (v).y * invH - cy;                                       \
        float r2 = sx * sx + sy * sy;                                       \
        float f  = 1.0f + alpha * r2;                                       \
        float ux = f * sx + cx;                                             \
        float uy = f * sy + cy;                                             \
        Sxx += ux * ux; Sxy += ux * uy; Syy += uy * uy; Sx += ux; Sy += uy; \
        sx = (v).z * invW - cx;                                             \
        sy = (v).w * invH - cy;                                             \
        r2 = sx * sx + sy * sy;                                             \
        f  = 1.0f + alpha * r2;                                             \
        ux = f * sx + cx;                                                   \
        uy = f * sy + cy;                                                   \
        Sxx += ux * ux; Sxy += ux * uy; Syy += uy * uy; Sx += ux; Sy += uy; \
    }

    ACC(v0) ACC(v1) ACC(v2) ACC(v3) ACC(v4) ACC(v5) ACC(v6) ACC(v7)
    #undef ACC

    #pragma unroll
    for (int o = 16; o > 0; o >>= 1) {
        Sxx += __shfl_xor_sync(0xffffffffu, Sxx, o);
        Sxy += __shfl_xor_sync(0xffffffffu, Sxy, o);
        Syy += __shfl_xor_sync(0xffffffffu, Syy, o);
        Sx  += __shfl_xor_sync(0xffffffffu, Sx,  o);
        Sy  += __shfl_xor_sync(0xffffffffu, Sy,  o);
    }

    __shared__ float sm[5];
    if (t < 5) sm[t] = 0.f;
    __syncthreads();
    if ((t & 31) == 0) {
        atomicAdd(&sm[0], Sxx);
        atomicAdd(&sm[1], Sxy);
        atomicAdd(&sm[2], Syy);
        atomicAdd(&sm[3], Sx);
        atomicAdd(&sm[4], Sy);
    }
    __syncthreads();

    if (t == 0) {
        // M = [[Sxx, Sxy, -Sx], [Sxy, Syy, -Sy], [-Sx, -Sy, N]]
        float m00 =  sm[0];
        float m01 =  sm[1];
        float m11 =  sm[2];
        float m02 = -sm[3];
        float m12 = -sm[4];
        float m22 =  (float)NPTS;

        // Newton on det(M - lam I) from lam = 0: monotone convergence for
        // SPD M with well-separated lam_min.
        float lam = 0.0f;
        #pragma unroll
        for (int it = 0; it < 6; it++) {
            float a00 = m00 - lam, a11 = m11 - lam, a22 = m22 - lam;
            float M0 = a11 * a22 - m12 * m12;
            float M1 = a00 * a22 - m02 * m02;
            float M2 = a00 * a11 - m01 * m01;
            float det = a00 * M0
                      - m01 * (m01 * a22 - m12 * m02)
                      + m02 * (m01 * m12 - a11 * m02);
            float dp = M0 + M1 + M2;           // = -p'(lam)
            lam += det / fmaxf(dp, 1e-20f);
        }

        // Eigenvector: largest cross product of rows of (M - lam I).
        float c00 = m00 - lam, c11 = m11 - lam, c22 = m22 - lam;

        float x0 = m01 * m12 - m02 * c11;
        float y0 = m02 * m01 - c00 * m12;
        float z0 = c00 * c11 - m01 * m01;
        float n0 = x0 * x0 + y0 * y0 + z0 * z0;

        float x1 = m01 * c22 - m02 * m12;
        float y1 = m02 * m02 - c00 * c22;
        float z1 = c00 * m12 - m01 * m02;
        float n1 = x1 * x1 + y1 * y1 + z1 * z1;

        float x2 = c11 * c22 - m12 * m12;
        float y2 = m12 * m02 - m01 * c22;
        float z2 = m01 * m12 - c11 * m02;
        float n2 = x2 * x2 + y2 * y2 + z2 * z2;

        float vx = x0, vy = y0, vz = z0, nbest = n0;
        if (n1 > nbest) { vx = x1; vy = y1; vz = z1; nbest = n1; }
        if (n2 > nbest) { vx = x2; vy = y2; vz = z2; nbest = n2; }

        // err = v^T M v / (vx^2 + vy^2)
        float vMv = m00 * vx * vx + m11 * vy * vy + m22 * vz * vz
                  + 2.0f * (m01 * vx * vy + m02 * vx * vz + m12 * vy * vz);
        float denom = vx * vx + vy * vy;
        out[l] = vMv / denom;
    }
}

extern "C" void kernel_launch(void* const* d_in, const int* in_sizes, int n_in,
                              void* d_out, int out_size)
{
    const float* input  = (const float*)d_in[0];
    const float* center = (const float*)d_in[1];
    const float* alpha  = (const float*)d_in[2];
    float* out = (float*)d_out;

    fused_kernel<<<LDIM, 128>>>(input, center, alpha, out);
}